// round 14
// baseline (speedup 1.0000x reference)
#include <cuda_runtime.h>
#include <cuda_fp16.h>
#include <math.h>
#include <stdint.h>

#define MTOK 65536   // 8 * 8192 tokens
#define D    128
#define HDIM 256
#define NLAYER 16
#define TTILE 128            // tokens per CTA
#define NCTA  (MTOK / TTILE) // 512
#define THREADS 512
#define WCHUNK 17408         // 128*136 halves per weight chunk (34816 B)
#define WBYTES 34816

// ======================= device global scratch ==============================
__device__ __half g_blocks[5][(size_t)MTOK * D];  // [0]=emb fp16, [1..4]=committed
__device__ __half g_w1c[(size_t)NLAYER * 2 * WCHUNK]; // padded chunks [l][c][128n][136k]
__device__ __half g_w2c[(size_t)NLAYER * 2 * WCHUNK]; // padded chunks [l][c][128n][136k]
__device__ float  g_part[(size_t)MTOK * D];       // fp32 running partial

// ======================= helpers ============================================
__device__ __forceinline__ uint32_t smem_u32(const void* p) {
    uint32_t a;
    asm("{ .reg .u64 t; cvta.to.shared.u64 t, %1; cvt.u32.u64 %0, t; }" : "=r"(a) : "l"(p));
    return a;
}
__device__ __forceinline__ uint32_t pack_h2(__half a, __half b) {
    return (uint32_t)__half_as_ushort(a) | ((uint32_t)__half_as_ushort(b) << 16);
}
__device__ __forceinline__ void ldm4(uint32_t* r, uint32_t addr) {
    asm volatile("ldmatrix.sync.aligned.m8n8.x4.shared.b16 {%0,%1,%2,%3}, [%4];"
                 : "=r"(r[0]), "=r"(r[1]), "=r"(r[2]), "=r"(r[3]) : "r"(addr));
}
__device__ __forceinline__ void mma16816(float* c, const uint32_t* a,
                                         uint32_t b0, uint32_t b1) {
    asm volatile("mma.sync.aligned.m16n8k16.row.col.f32.f16.f16.f32 "
                 "{%0,%1,%2,%3}, {%4,%5,%6,%7}, {%8,%9}, {%0,%1,%2,%3};"
                 : "+f"(c[0]), "+f"(c[1]), "+f"(c[2]), "+f"(c[3])
                 : "r"(a[0]), "r"(a[1]), "r"(a[2]), "r"(a[3]), "r"(b0), "r"(b1));
}

// ---- bulk-async weight fill (one UBLKCP per 34816-byte chunk) ----
__device__ __forceinline__ void mbar_init(uint32_t mbar, uint32_t cnt) {
    asm volatile("mbarrier.init.shared.b64 [%0], %1;" :: "r"(mbar), "r"(cnt) : "memory");
}
__device__ __forceinline__ void fill_w_bulk(uint32_t dstSmem, const __half* src,
                                            uint32_t mbar, int tid) {
    if (tid == 0) {
        asm volatile("mbarrier.arrive.expect_tx.shared.b64 _, [%0], %1;"
                     :: "r"(mbar), "r"((uint32_t)WBYTES) : "memory");
        asm volatile("cp.async.bulk.shared::cta.global.mbarrier::complete_tx::bytes "
                     "[%0], [%1], %2, [%3];"
                     :: "r"(dstSmem), "l"(src), "r"((uint32_t)WBYTES), "r"(mbar)
                     : "memory");
    }
}
__device__ __forceinline__ void mbar_wait(uint32_t mbar, int phase) {
    uint32_t done;
    do {
        asm volatile("{\n\t.reg .pred p;\n\t"
            "mbarrier.try_wait.parity.shared.b64 p, [%1], %2;\n\t"
            "selp.b32 %0, 1, 0, p;\n\t}" : "=r"(done) : "r"(mbar), "r"((uint32_t)phase)
            : "memory");
    } while (!done);
}

__device__ __forceinline__ float wsum16(float v) {
#pragma unroll
    for (int o = 8; o > 0; o >>= 1) v += __shfl_xor_sync(0xffffffffu, v, o);
    return v;
}

// Fast exact-GELU: branch-free A&S 7.1.26 erf (|abs err| <= 1.5e-7)
__device__ __forceinline__ float gelu_f(float x) {
    float z  = x * 0.70710678118654752f;
    float az = fabsf(z);
    float t  = __frcp_rn(fmaf(0.3275911f, az, 1.0f));
    float p  = fmaf(1.061405429f, t, -1.453152027f);
    p = fmaf(p, t, 1.421413741f);
    p = fmaf(p, t, -0.284496736f);
    p = fmaf(p, t, 0.254829592f);
    p = p * t;
    float e  = __expf(-z * z);
    float er = copysignf(fmaf(-p, e, 1.0f), z);
    return 0.5f * x * (1.0f + er);
}

// ======================= smem layout ========================================
#define SP_XN    0                      // half [128][136]          34816
#define SP_HID0  34816                  // half [128][136]          34816
#define SP_HID1  69632                  // half [128][136]          34816
#define SP_W     104448                 // 3 x half [128][136]     104448
#define SP_INV   208896                 // fp32 [4][128]             2048
#define SP_MBAR  210944                 // 3 mbarriers                24
#define SMEM_TOTAL 210968

// 128x128x128 tile accumulation; A and B both stride 136 halves
__device__ __forceinline__ void gemm_tile(uint32_t sbA, uint32_t sbB,
                                          float acc[2][4][4], int wm, int wn,
                                          int a_r, int a_k, int b_r, int b_k) {
#pragma unroll
    for (int k16 = 0; k16 < 128; k16 += 16) {
        uint32_t a[2][4], b[2][4];
#pragma unroll
        for (int mi = 0; mi < 2; mi++)
            ldm4(a[mi], sbA + (uint32_t)((wm + mi * 16 + a_r) * 136 + k16 + a_k) * 2);
#pragma unroll
        for (int np = 0; np < 2; np++)
            ldm4(b[np], sbB + (uint32_t)((wn + np * 16 + b_r) * 136 + k16 + b_k) * 2);
#pragma unroll
        for (int mi = 0; mi < 2; mi++) {
            mma16816(acc[mi][0], a[mi], b[0][0], b[0][1]);
            mma16816(acc[mi][1], a[mi], b[0][2], b[0][3]);
            mma16816(acc[mi][2], a[mi], b[1][0], b[1][1]);
            mma16816(acc[mi][3], a[mi], b[1][2], b[1][3]);
        }
    }
}

#define ACC_CLEAR(acc)                                 \
    _Pragma("unroll") for (int i = 0; i < 2; i++)      \
    _Pragma("unroll") for (int j = 0; j < 4; j++)      \
    _Pragma("unroll") for (int q = 0; q < 4; q++) acc[i][j][q] = 0.f;

// ======================= fused whole-network kernel =========================
__global__ __launch_bounds__(THREADS, 1)
void fused_net(const float* __restrict__ w, const float* __restrict__ ln_g,
               const float* __restrict__ ln_b, const float* __restrict__ b1,
               const float* __restrict__ b2, float* __restrict__ out) {
    extern __shared__ char smem[];
    __half* sXn   = (__half*)(smem + SP_XN);
    __half* sHid0 = (__half*)(smem + SP_HID0);
    __half* sHid1 = (__half*)(smem + SP_HID1);
    float*  sInv  = (float*)(smem + SP_INV);
    const uint32_t sbXn   = smem_u32(sXn);
    const uint32_t sbHid0 = smem_u32(sHid0);
    const uint32_t sbHid1 = smem_u32(sHid1);
    uint32_t sbW[3], mb[3];
    int ph[3] = {0, 0, 0};
#pragma unroll
    for (int i = 0; i < 3; i++) {
        sbW[i] = smem_u32(smem + SP_W + i * WBYTES);
        mb[i]  = smem_u32(smem + SP_MBAR) + 8 * i;
    }

    const int tid  = threadIdx.x;
    const int wid  = tid >> 5;
    const int lane = tid & 31;
    const int bm   = blockIdx.x * TTILE;

    // warp tiling: 16 warps = 4m x 4n, warp tile 32x32
    const int wm = (wid >> 2) * 32;
    const int wn = (wid & 3) * 32;
    const int a_r = (lane & 15);
    const int a_k = (lane >> 4) << 3;
    const int b_r = (lane & 7) + ((lane >> 4) << 3);
    const int b_k = ((lane >> 3) & 1) << 3;
    const int g  = lane >> 2;
    const int t4 = lane & 3;

    // mix coords: 16 lanes/token, 8 dims/lane, 32 tokens per pass
    const int mtok0 = tid >> 4;
    const int l16   = tid & 15;

    const __half* gb = &g_blocks[0][0];
    float* gp = g_part + (size_t)bm * D;

    if (tid == 0) { mbar_init(mb[0], 1); mbar_init(mb[1], 1); mbar_init(mb[2], 1); }
    __syncthreads();
    // prologue: layer-0 W1 chunks into buffers 0, 1
    fill_w_bulk(sbW[0], g_w1c,          mb[0], tid);
    fill_w_bulk(sbW[1], g_w1c + WCHUNK, mb[1], tid);

    int ra = 0;   // rotating buffer index

    for (int l = 0; l < NLAYER; l++) {
        const int grp = l >> 2;
        const int hasPartial = (l & 3) != 0;
        const int nsg = 1 + grp;
        const __half* w2l = g_w2c + (size_t)l * 2 * WCHUNK;
        const int ba = ra, bb = (ra + 1) % 3, bc = (ra + 2) % 3;

        // ---------------- mix phase ----------------
        {
            const float* wrow = w + l * D;
            float wv[8], gg[8], bbv[8];
            {
                float4 a0 = *(const float4*)(wrow + l16 * 8);
                float4 a1 = *(const float4*)(wrow + l16 * 8 + 4);
                wv[0]=a0.x; wv[1]=a0.y; wv[2]=a0.z; wv[3]=a0.w;
                wv[4]=a1.x; wv[5]=a1.y; wv[6]=a1.z; wv[7]=a1.w;
            }
            if (l < NLAYER - 1) {
                float4 a0 = *(const float4*)(ln_g + l * D + l16 * 8);
                float4 a1 = *(const float4*)(ln_g + l * D + l16 * 8 + 4);
                gg[0]=a0.x; gg[1]=a0.y; gg[2]=a0.z; gg[3]=a0.w;
                gg[4]=a1.x; gg[5]=a1.y; gg[6]=a1.z; gg[7]=a1.w;
                float4 c0 = *(const float4*)(ln_b + l * D + l16 * 8);
                float4 c1 = *(const float4*)(ln_b + l * D + l16 * 8 + 4);
                bbv[0]=c0.x; bbv[1]=c0.y; bbv[2]=c0.z; bbv[3]=c0.w;
                bbv[4]=c1.x; bbv[5]=c1.y; bbv[6]=c1.z; bbv[7]=c1.w;
            }
#pragma unroll 1
            for (int it = 0; it < 4; it++) {
                int tg = it * 32 + mtok0;
                float v[5][8];
                float lgt[5];
                int n = 0;
#pragma unroll
                for (int i = 0; i < 4; i++) {
                    if (i < nsg) {
                        uint4 raw = *(const uint4*)(gb + ((size_t)i * MTOK + bm + tg) * D + l16 * 8);
                        const uint32_t* pr = (const uint32_t*)&raw;
#pragma unroll
                        for (int q = 0; q < 4; q++) {
                            float2 f = __half22float2(*(const __half2*)&pr[q]);
                            v[i][2 * q] = f.x; v[i][2 * q + 1] = f.y;
                        }
                        float dt = 0.f;
#pragma unroll
                        for (int j = 0; j < 8; j++) dt += wv[j] * v[i][j];
                        float dtr = wsum16(dt);
                        float ir;
                        if (l == 4 * i) {           // source is new: compute + cache
                            float ss = 0.f;
#pragma unroll
                            for (int j = 0; j < 8; j++) ss += v[i][j] * v[i][j];
                            ss = wsum16(ss);
                            ir = rsqrtf(ss * (1.0f / D) + 1e-8f);
                            if (l16 == 0) sInv[i * 128 + tg] = ir;
                        } else {
                            ir = sInv[i * 128 + tg];
                        }
                        lgt[i] = dtr * ir;
                        n++;
                    }
                }
                if (hasPartial) {
                    const float* pp = gp + tg * D + l16 * 8;
                    float4 p0v = *(const float4*)pp;
                    float4 p1v = *(const float4*)(pp + 4);
                    v[n][0]=p0v.x; v[n][1]=p0v.y; v[n][2]=p0v.z; v[n][3]=p0v.w;
                    v[n][4]=p1v.x; v[n][5]=p1v.y; v[n][6]=p1v.z; v[n][7]=p1v.w;
                    float ss = 0.f, dt = 0.f;
#pragma unroll
                    for (int j = 0; j < 8; j++) { ss += v[n][j]*v[n][j]; dt += wv[j]*v[n][j]; }
                    ss = wsum16(ss);
                    dt = wsum16(dt);
                    lgt[n] = dt * rsqrtf(ss * (1.0f / D) + 1e-8f);
                    n++;
                }
                float mx = -1e30f;
#pragma unroll
                for (int i = 0; i < 5; i++) if (i < n) mx = fmaxf(mx, lgt[i]);
                float se = 0.f;
#pragma unroll
                for (int i = 0; i < 5; i++) if (i < n) { lgt[i] = __expf(lgt[i] - mx); se += lgt[i]; }
                float inv = __frcp_rn(se);
                float h[8];
#pragma unroll
                for (int j = 0; j < 8; j++) h[j] = 0.f;
#pragma unroll
                for (int i = 0; i < 5; i++) if (i < n) {
                    float wt = lgt[i] * inv;
#pragma unroll
                    for (int j = 0; j < 8; j++) h[j] += wt * v[i][j];
                }

                if (l == NLAYER - 1) {
                    float* op = out + (size_t)(bm + tg) * D + l16 * 8;
                    float4 o0 = {h[0], h[1], h[2], h[3]};
                    float4 o1 = {h[4], h[5], h[6], h[7]};
                    *(float4*)op = o0;
                    *(float4*)(op + 4) = o1;
                } else {
                    float s = 0.f;
#pragma unroll
                    for (int j = 0; j < 8; j++) s += h[j];
                    float mu = wsum16(s) * (1.0f / D);
                    float vs = 0.f;
#pragma unroll
                    for (int j = 0; j < 8; j++) { float d0 = h[j] - mu; vs += d0 * d0; }
                    float var = wsum16(vs) * (1.0f / D);
                    float r = rsqrtf(var + 1e-5f);
                    uint32_t pk[4];
#pragma unroll
                    for (int q = 0; q < 4; q++) {
                        float o0 = (h[2*q]   - mu) * r * gg[2*q]   + bbv[2*q];
                        float o1 = (h[2*q+1] - mu) * r * gg[2*q+1] + bbv[2*q+1];
                        pk[q] = pack_h2(__float2half_rn(o0), __float2half_rn(o1));
                    }
                    *(uint2*)(sXn + tg * 136 + l16 * 8)     = make_uint2(pk[0], pk[1]);
                    *(uint2*)(sXn + tg * 136 + l16 * 8 + 4) = make_uint2(pk[2], pk[3]);
                }
            }
        }
        if (l == NLAYER - 1) return;

        __syncthreads();                        // sXn ready
        mbar_wait(mb[ba], ph[ba] & 1); ph[ba]++;   // W1c0
        mbar_wait(mb[bb], ph[bb] & 1); ph[bb]++;   // W1c1
        fill_w_bulk(sbW[bc], w2l, mb[bc], tid);    // prefetch W2k0 -> c

        float acc[2][4][4];

        // ===== gemm1: both chunks, no intervening barrier =====
        ACC_CLEAR(acc);
        gemm_tile(sbXn, sbW[ba], acc, wm, wn, a_r, a_k, b_r, b_k);
#pragma unroll
        for (int mi = 0; mi < 2; mi++)
#pragma unroll
            for (int nj = 0; nj < 4; nj++) {
                int cc = wn + nj * 8 + 2 * t4;
                float bv0 = __ldg(b1 + l * HDIM + cc);
                float bv1 = __ldg(b1 + l * HDIM + cc + 1);
#pragma unroll
                for (int hh = 0; hh < 2; hh++) {
                    int row = wm + mi * 16 + g + hh * 8;
                    float y0 = gelu_f(acc[mi][nj][2 * hh]     + bv0);
                    float y1 = gelu_f(acc[mi][nj][2 * hh + 1] + bv1);
                    *(uint32_t*)(sHid0 + row * 136 + cc) =
                        pack_h2(__float2half_rn(y0), __float2half_rn(y1));
                }
            }
        ACC_CLEAR(acc);
        gemm_tile(sbXn, sbW[bb], acc, wm, wn, a_r, a_k, b_r, b_k);
#pragma unroll
        for (int mi = 0; mi < 2; mi++)
#pragma unroll
            for (int nj = 0; nj < 4; nj++) {
                int cc = wn + nj * 8 + 2 * t4;
                float bv0 = __ldg(b1 + l * HDIM + 128 + cc);
                float bv1 = __ldg(b1 + l * HDIM + 128 + cc + 1);
#pragma unroll
                for (int hh = 0; hh < 2; hh++) {
                    int row = wm + mi * 16 + g + hh * 8;
                    float y0 = gelu_f(acc[mi][nj][2 * hh]     + bv0);
                    float y1 = gelu_f(acc[mi][nj][2 * hh + 1] + bv1);
                    *(uint32_t*)(sHid1 + row * 136 + cc) =
                        pack_h2(__float2half_rn(y0), __float2half_rn(y1));
                }
            }

        __syncthreads();                        // sHid ready; a,b buffers free
        fill_w_bulk(sbW[ba], w2l + WCHUNK, mb[ba], tid);   // W2k1 -> a
        if (l < NLAYER - 2)
            fill_w_bulk(sbW[bb], g_w1c + (size_t)(l + 1) * 2 * WCHUNK, mb[bb], tid); // next W1c0 -> b

        // ===== gemm2: K=256, single accumulator =====
        mbar_wait(mb[bc], ph[bc] & 1); ph[bc]++;   // W2k0
        ACC_CLEAR(acc);
        gemm_tile(sbHid0, sbW[bc], acc, wm, wn, a_r, a_k, b_r, b_k);
        mbar_wait(mb[ba], ph[ba] & 1); ph[ba]++;   // W2k1
        gemm_tile(sbHid1, sbW[ba], acc, wm, wn, a_r, a_k, b_r, b_k);
        {
            const int commit = ((l & 3) == 3);
            __half* cb = commit ? (&g_blocks[grp + 1][0] + (size_t)bm * D) : (__half*)0;
#pragma unroll
            for (int mi = 0; mi < 2; mi++)
#pragma unroll
                for (int nj = 0; nj < 4; nj++) {
                    int cc = wn + nj * 8 + 2 * t4;
                    float bv0 = __ldg(b2 + l * D + cc);
                    float bv1 = __ldg(b2 + l * D + cc + 1);
#pragma unroll
                    for (int hh = 0; hh < 2; hh++) {
                        int row = wm + mi * 16 + g + hh * 8;
                        float x0 = acc[mi][nj][2 * hh]     + bv0;
                        float x1 = acc[mi][nj][2 * hh + 1] + bv1;
                        float* pp = gp + row * D + cc;
                        if (hasPartial) {
                            float2 o = *(const float2*)pp;
                            x0 += o.x; x1 += o.y;
                        }
                        float2 vv = {x0, x1};
                        *(float2*)pp = vv;
                        if (commit)
                            *(uint32_t*)(cb + (size_t)row * D + cc) =
                                pack_h2(__float2half_rn(x0), __float2half_rn(x1));
                    }
                }
        }
        __syncthreads();                        // partial visible; c free
        if (l < NLAYER - 2)
            fill_w_bulk(sbW[bc], g_w1c + (size_t)(l + 1) * 2 * WCHUNK + WCHUNK, mb[bc], tid); // next W1c1 -> c

        ra = bb;   // rotate: next layer a'=b (W1c0), b'=c (W1c1), c'=a (free)
    }
}

// ======================= prep kernels =======================================
// Coalesced transpose + fp16, writing the PADDED chunk layout (stride 136).
__global__ void transpose_w(const float* __restrict__ W1, const float* __restrict__ W2) {
    __shared__ float tile[32][33];
    int b = blockIdx.x;              // 16 layers * 64 tiles
    int lay = b >> 6, t = b & 63;
    int x = threadIdx.x, y = threadIdx.y;    // (32, 8)
    if (t < 32) {                    // W1: in [128 k][256 n] -> chunks [2][128 n][136 k]
        const float* in = W1 + (size_t)lay * D * HDIM;
        __half* outp = g_w1c + (size_t)lay * 2 * WCHUNK;
        int tr = t >> 3, tc = t & 7;
#pragma unroll
        for (int yy = 0; yy < 4; yy++) {
            int r = y * 4 + yy;
            tile[r][x] = in[(size_t)(tr * 32 + r) * HDIM + tc * 32 + x];
        }
        __syncthreads();
#pragma unroll
        for (int yy = 0; yy < 4; yy++) {
            int r = y * 4 + yy;
            int n = tc * 32 + r, k = tr * 32 + x;
            outp[(size_t)(n >> 7) * WCHUNK + (n & 127) * 136 + k] = __float2half_rn(tile[x][r]);
        }
    } else {                         // W2: in [256 k][128 n] -> chunks [2][128 n][136 k]
        int tt = t - 32;
        const float* in = W2 + (size_t)lay * HDIM * D;
        __half* outp = g_w2c + (size_t)lay * 2 * WCHUNK;
        int tr = tt >> 2, tc = tt & 3;
#pragma unroll
        for (int yy = 0; yy < 4; yy++) {
            int r = y * 4 + yy;
            tile[r][x] = in[(size_t)(tr * 32 + r) * D + tc * 32 + x];
        }
        __syncthreads();
#pragma unroll
        for (int yy = 0; yy < 4; yy++) {
            int r = y * 4 + yy;
            int n = tc * 32 + r, k = tr * 32 + x;
            outp[(size_t)(k >> 7) * WCHUNK + n * 136 + (k & 127)] = __float2half_rn(tile[x][r]);
        }
    }
}

__global__ void conv_emb(const float* __restrict__ emb) {
    const size_t N = (size_t)MTOK * D;
    for (size_t i = (size_t)blockIdx.x * blockDim.x + threadIdx.x; i < N;
         i += (size_t)gridDim.x * blockDim.x)
        g_blocks[0][i] = __float2half_rn(emb[i]);
}

// ======================= host orchestration =================================
extern "C" void kernel_launch(void* const* d_in, const int* in_sizes, int n_in,
                              void* d_out, int out_size) {
    const float* emb  = (const float*)d_in[0];
    const float* w    = (const float*)d_in[1];
    const float* ln_g = (const float*)d_in[2];
    const float* ln_b = (const float*)d_in[3];
    const float* W1   = (const float*)d_in[4];
    const float* b1   = (const float*)d_in[5];
    const float* W2   = (const float*)d_in[6];
    const float* b2   = (const float*)d_in[7];
    float* out = (float*)d_out;

    cudaFuncSetAttribute(fused_net, cudaFuncAttributeMaxDynamicSharedMemorySize, SMEM_TOTAL);

    transpose_w<<<NLAYER * 64, dim3(32, 8)>>>(W1, W2);
    conv_emb<<<512, 256>>>(emb);
    fused_net<<<NCTA, THREADS, SMEM_TOTAL>>>(w, ln_g, ln_b, b1, b2, out);
}

// round 15
// speedup vs baseline: 1.1156x; 1.1156x over previous
#include <cuda_runtime.h>
#include <cuda_fp16.h>
#include <math.h>
#include <stdint.h>

#define MTOK 65536   // 8 * 8192 tokens
#define D    128
#define HDIM 256
#define NLAYER 16
#define TTILE 128            // tokens per CTA
#define NCTA  (MTOK / TTILE) // 512
#define THREADS 512
#define WCHUNK 17408         // 128*136 halves per weight chunk (34816 B)

// ======================= device global scratch ==============================
__device__ __half g_blocks[5][(size_t)MTOK * D];  // [0]=emb fp16, [1..4]=committed
__device__ __half g_w1c[(size_t)NLAYER * 2 * WCHUNK]; // padded chunks [l][c][128n][136k]
__device__ __half g_w2c[(size_t)NLAYER * 2 * WCHUNK]; // padded chunks [l][c][128n][136k]

// ======================= helpers ============================================
__device__ __forceinline__ uint32_t smem_u32(const void* p) {
    uint32_t a;
    asm("{ .reg .u64 t; cvta.to.shared.u64 t, %1; cvt.u32.u64 %0, t; }" : "=r"(a) : "l"(p));
    return a;
}
__device__ __forceinline__ uint32_t pack_h2(__half a, __half b) {
    return (uint32_t)__half_as_ushort(a) | ((uint32_t)__half_as_ushort(b) << 16);
}
__device__ __forceinline__ void ldm4(uint32_t* r, uint32_t addr) {
    asm volatile("ldmatrix.sync.aligned.m8n8.x4.shared.b16 {%0,%1,%2,%3}, [%4];"
                 : "=r"(r[0]), "=r"(r[1]), "=r"(r[2]), "=r"(r[3]) : "r"(addr));
}
__device__ __forceinline__ void mma16816(float* c, const uint32_t* a,
                                         uint32_t b0, uint32_t b1) {
    asm volatile("mma.sync.aligned.m16n8k16.row.col.f32.f16.f16.f32 "
                 "{%0,%1,%2,%3}, {%4,%5,%6,%7}, {%8,%9}, {%0,%1,%2,%3};"
                 : "+f"(c[0]), "+f"(c[1]), "+f"(c[2]), "+f"(c[3])
                 : "r"(a[0]), "r"(a[1]), "r"(a[2]), "r"(a[3]), "r"(b0), "r"(b1));
}

// ---- bulk-async weight fill (one UBLKCP per 34816-byte chunk) ----
__device__ __forceinline__ void mbar_init(uint32_t mbar, uint32_t cnt) {
    asm volatile("mbarrier.init.shared.b64 [%0], %1;" :: "r"(mbar), "r"(cnt) : "memory");
}
__device__ __forceinline__ void fill_w_bulk(uint32_t dstSmem, const __half* src,
                                            uint32_t mbar, int tid) {
    if (tid == 0) {
        asm volatile("mbarrier.arrive.expect_tx.shared.b64 _, [%0], %1;"
                     :: "r"(mbar), "r"((uint32_t)(WCHUNK * 2)) : "memory");
        asm volatile("cp.async.bulk.shared::cta.global.mbarrier::complete_tx::bytes "
                     "[%0], [%1], %2, [%3];"
                     :: "r"(dstSmem), "l"(src), "r"((uint32_t)(WCHUNK * 2)), "r"(mbar)
                     : "memory");
    }
}
__device__ __forceinline__ void mbar_wait(uint32_t mbar, int phase) {
    uint32_t done;
    do {
        asm volatile("{\n\t.reg .pred p;\n\t"
            "mbarrier.try_wait.parity.shared.b64 p, [%1], %2;\n\t"
            "selp.b32 %0, 1, 0, p;\n\t}" : "=r"(done) : "r"(mbar), "r"((uint32_t)phase)
            : "memory");
    } while (!done);
}

__device__ __forceinline__ float wsum16(float v) {
#pragma unroll
    for (int o = 8; o > 0; o >>= 1) v += __shfl_xor_sync(0xffffffffu, v, o);
    return v;
}

// Fast exact-GELU: branch-free A&S 7.1.26 erf (|abs err| <= 1.5e-7)
__device__ __forceinline__ float gelu_f(float x) {
    float z  = x * 0.70710678118654752f;
    float az = fabsf(z);
    float t  = __frcp_rn(fmaf(0.3275911f, az, 1.0f));
    float p  = fmaf(1.061405429f, t, -1.453152027f);
    p = fmaf(p, t, 1.421413741f);
    p = fmaf(p, t, -0.284496736f);
    p = fmaf(p, t, 0.254829592f);
    p = p * t;
    float e  = __expf(-z * z);
    float er = copysignf(fmaf(-p, e, 1.0f), z);
    return 0.5f * x * (1.0f + er);
}

// ======================= smem layout ========================================
#define PSTRIDE 132                     // fp32 partial row stride (pad vs 128)
#define SP_PART 0                       // fp32 [128][132]          67584
#define SP_XN   67584                   // half [128][136]          34816
#define SP_HID  102400                  // half [128][136]          34816
#define SP_W0   137216                  // half [128][136]          34816
#define SP_W1   172032                  // half [128][136]          34816
#define SP_INV  206848                  // fp32 [4][128]             2048
#define SP_MBAR 208896                  // 2 mbarriers (8B each)       16
#define SMEM_TOTAL 208912

// 128x128x128 tile accumulation; A and B both stride 136 halves
__device__ __forceinline__ void gemm_tile(uint32_t sbA, uint32_t sbB,
                                          float acc[2][4][4], int wm, int wn,
                                          int a_r, int a_k, int b_r, int b_k) {
#pragma unroll
    for (int k16 = 0; k16 < 128; k16 += 16) {
        uint32_t a[2][4], b[2][4];
#pragma unroll
        for (int mi = 0; mi < 2; mi++)
            ldm4(a[mi], sbA + (uint32_t)((wm + mi * 16 + a_r) * 136 + k16 + a_k) * 2);
#pragma unroll
        for (int np = 0; np < 2; np++)
            ldm4(b[np], sbB + (uint32_t)((wn + np * 16 + b_r) * 136 + k16 + b_k) * 2);
#pragma unroll
        for (int mi = 0; mi < 2; mi++) {
            mma16816(acc[mi][0], a[mi], b[0][0], b[0][1]);
            mma16816(acc[mi][1], a[mi], b[0][2], b[0][3]);
            mma16816(acc[mi][2], a[mi], b[1][0], b[1][1]);
            mma16816(acc[mi][3], a[mi], b[1][2], b[1][3]);
        }
    }
}

#define ACC_CLEAR(acc)                                 \
    _Pragma("unroll") for (int i = 0; i < 2; i++)      \
    _Pragma("unroll") for (int j = 0; j < 4; j++)      \
    _Pragma("unroll") for (int q = 0; q < 4; q++) acc[i][j][q] = 0.f;

// ======================= fused whole-network kernel =========================
__global__ __launch_bounds__(THREADS, 1)
void fused_net(const float* __restrict__ w, const float* __restrict__ ln_g,
               const float* __restrict__ ln_b, const float* __restrict__ b1,
               const float* __restrict__ b2, float* __restrict__ out) {
    extern __shared__ char smem[];
    float*  sPart = (float*)(smem + SP_PART);
    __half* sXn   = (__half*)(smem + SP_XN);
    __half* sHid  = (__half*)(smem + SP_HID);
    float*  sInv  = (float*)(smem + SP_INV);
    const uint32_t sbXn  = smem_u32(sXn);
    const uint32_t sbHid = smem_u32(sHid);
    const uint32_t sbW0  = smem_u32(smem + SP_W0);
    const uint32_t sbW1  = smem_u32(smem + SP_W1);
    const uint32_t mb0   = smem_u32(smem + SP_MBAR);
    const uint32_t mb1   = mb0 + 8;

    const int tid  = threadIdx.x;
    const int wid  = tid >> 5;
    const int lane = tid & 31;
    const int bm   = blockIdx.x * TTILE;

    // warp tiling: 16 warps = 4m x 4n, warp tile 32x32
    const int wm = (wid >> 2) * 32;
    const int wn = (wid & 3) * 32;
    const int a_r = (lane & 15);
    const int a_k = (lane >> 4) << 3;
    const int b_r = (lane & 7) + ((lane >> 4) << 3);
    const int b_k = ((lane >> 3) & 1) << 3;
    const int g  = lane >> 2;
    const int t4 = lane & 3;

    // mix coords: 16 lanes/token, 8 dims/lane, 32 tokens per pass
    const int mtok0 = tid >> 4;
    const int l16   = tid & 15;

    const __half* gb = &g_blocks[0][0];
    int p0 = 0, p1 = 0;   // mbarrier phases

    if (tid == 0) { mbar_init(mb0, 1); mbar_init(mb1, 1); }
    __syncthreads();
    // prefetch layer-0 W1 chunk0 into buf0
    fill_w_bulk(sbW0, g_w1c, mb0, tid);

    for (int l = 0; l < NLAYER; l++) {
        const int grp = l >> 2;
        const int hasPartial = (l & 3) != 0;
        const int nsg = 1 + grp;
        const __half* w1l = g_w1c + (size_t)l * 2 * WCHUNK;
        const __half* w2l = g_w2c + (size_t)l * 2 * WCHUNK;

        // ---------------- mix phase (software-pipelined source loads) -------
        {
            const float* wrow = w + l * D;
            float wv[8], gg[8], bb[8];
            {
                float4 a0 = *(const float4*)(wrow + l16 * 8);
                float4 a1 = *(const float4*)(wrow + l16 * 8 + 4);
                wv[0]=a0.x; wv[1]=a0.y; wv[2]=a0.z; wv[3]=a0.w;
                wv[4]=a1.x; wv[5]=a1.y; wv[6]=a1.z; wv[7]=a1.w;
            }
            if (l < NLAYER - 1) {
                float4 a0 = *(const float4*)(ln_g + l * D + l16 * 8);
                float4 a1 = *(const float4*)(ln_g + l * D + l16 * 8 + 4);
                gg[0]=a0.x; gg[1]=a0.y; gg[2]=a0.z; gg[3]=a0.w;
                gg[4]=a1.x; gg[5]=a1.y; gg[6]=a1.z; gg[7]=a1.w;
                float4 c0 = *(const float4*)(ln_b + l * D + l16 * 8);
                float4 c1 = *(const float4*)(ln_b + l * D + l16 * 8 + 4);
                bb[0]=c0.x; bb[1]=c0.y; bb[2]=c0.z; bb[3]=c0.w;
                bb[4]=c1.x; bb[5]=c1.y; bb[6]=c1.z; bb[7]=c1.w;
            }

            // preload iteration 0's gmem sources
            uint4 raw[4];
#pragma unroll
            for (int i = 0; i < 4; i++)
                if (i < nsg)
                    raw[i] = *(const uint4*)(gb + ((size_t)i * MTOK + bm + mtok0) * D + l16 * 8);

#pragma unroll 1
            for (int it = 0; it < 4; it++) {
                int tg = it * 32 + mtok0;
                uint4 cur[4];
#pragma unroll
                for (int i = 0; i < 4; i++) if (i < nsg) cur[i] = raw[i];
                if (it < 3) {
                    int tgn = tg + 32;
#pragma unroll
                    for (int i = 0; i < 4; i++)
                        if (i < nsg)
                            raw[i] = *(const uint4*)(gb + ((size_t)i * MTOK + bm + tgn) * D + l16 * 8);
                }

                float v[5][8];
                float lgt[5];
                int n = 0;
#pragma unroll
                for (int i = 0; i < 4; i++) {
                    if (i < nsg) {
                        const uint32_t* pr = (const uint32_t*)&cur[i];
#pragma unroll
                        for (int q = 0; q < 4; q++) {
                            float2 f = __half22float2(*(const __half2*)&pr[q]);
                            v[i][2 * q] = f.x; v[i][2 * q + 1] = f.y;
                        }
                        float dt = 0.f;
#pragma unroll
                        for (int j = 0; j < 8; j++) dt += wv[j] * v[i][j];
                        float dtr = wsum16(dt);
                        float ir;
                        if (l == 4 * i) {           // source is new: compute + cache
                            float ss = 0.f;
#pragma unroll
                            for (int j = 0; j < 8; j++) ss += v[i][j] * v[i][j];
                            ss = wsum16(ss);
                            ir = rsqrtf(ss * (1.0f / D) + 1e-8f);
                            if (l16 == 0) sInv[i * 128 + tg] = ir;
                        } else {
                            ir = sInv[i * 128 + tg];
                        }
                        lgt[i] = dtr * ir;
                        n++;
                    }
                }
                if (hasPartial) {
                    const float* pp = sPart + tg * PSTRIDE + l16 * 8;
                    float4 p0v = *(const float4*)pp;
                    float4 p1v = *(const float4*)(pp + 4);
                    v[n][0]=p0v.x; v[n][1]=p0v.y; v[n][2]=p0v.z; v[n][3]=p0v.w;
                    v[n][4]=p1v.x; v[n][5]=p1v.y; v[n][6]=p1v.z; v[n][7]=p1v.w;
                    float ss = 0.f, dt = 0.f;
#pragma unroll
                    for (int j = 0; j < 8; j++) { ss += v[n][j]*v[n][j]; dt += wv[j]*v[n][j]; }
                    ss = wsum16(ss);
                    dt = wsum16(dt);
                    lgt[n] = dt * rsqrtf(ss * (1.0f / D) + 1e-8f);
                    n++;
                }
                float mx = -1e30f;
#pragma unroll
                for (int i = 0; i < 5; i++) if (i < n) mx = fmaxf(mx, lgt[i]);
                float se = 0.f;
#pragma unroll
                for (int i = 0; i < 5; i++) if (i < n) { lgt[i] = __expf(lgt[i] - mx); se += lgt[i]; }
                float inv = __frcp_rn(se);
                float h[8];
#pragma unroll
                for (int j = 0; j < 8; j++) h[j] = 0.f;
#pragma unroll
                for (int i = 0; i < 5; i++) if (i < n) {
                    float wt = lgt[i] * inv;
#pragma unroll
                    for (int j = 0; j < 8; j++) h[j] += wt * v[i][j];
                }

                if (l == NLAYER - 1) {
                    float* op = out + (size_t)(bm + tg) * D + l16 * 8;
                    float4 o0 = {h[0], h[1], h[2], h[3]};
                    float4 o1 = {h[4], h[5], h[6], h[7]};
                    *(float4*)op = o0;
                    *(float4*)(op + 4) = o1;
                } else {
                    float s = 0.f;
#pragma unroll
                    for (int j = 0; j < 8; j++) s += h[j];
                    float mu = wsum16(s) * (1.0f / D);
                    float vs = 0.f;
#pragma unroll
                    for (int j = 0; j < 8; j++) { float d0 = h[j] - mu; vs += d0 * d0; }
                    float var = wsum16(vs) * (1.0f / D);
                    float r = rsqrtf(var + 1e-5f);
                    uint32_t pk[4];
#pragma unroll
                    for (int q = 0; q < 4; q++) {
                        float o0 = (h[2*q]   - mu) * r * gg[2*q]   + bb[2*q];
                        float o1 = (h[2*q+1] - mu) * r * gg[2*q+1] + bb[2*q+1];
                        pk[q] = pack_h2(__float2half_rn(o0), __float2half_rn(o1));
                    }
                    *(uint2*)(sXn + tg * 136 + l16 * 8)     = make_uint2(pk[0], pk[1]);
                    *(uint2*)(sXn + tg * 136 + l16 * 8 + 4) = make_uint2(pk[2], pk[3]);
                }
            }
        }
        if (l == NLAYER - 1) return;

        float acc[2][4][4];

        // ===== Phase A: gemm1 ch0  (W1c0 in buf0) =====
        mbar_wait(mb0, p0); p0 ^= 1;
        __syncthreads();
        fill_w_bulk(sbW1, w2l, mb1, tid);      // prefetch W2 khalf0
        ACC_CLEAR(acc);
        gemm_tile(sbXn, sbW0, acc, wm, wn, a_r, a_k, b_r, b_k);
#pragma unroll
        for (int mi = 0; mi < 2; mi++)
#pragma unroll
            for (int nj = 0; nj < 4; nj++) {
                int cc = wn + nj * 8 + 2 * t4;
                float bv0 = __ldg(b1 + l * HDIM + cc);
                float bv1 = __ldg(b1 + l * HDIM + cc + 1);
#pragma unroll
                for (int hh = 0; hh < 2; hh++) {
                    int row = wm + mi * 16 + g + hh * 8;
                    float y0 = gelu_f(acc[mi][nj][2 * hh]     + bv0);
                    float y1 = gelu_f(acc[mi][nj][2 * hh + 1] + bv1);
                    *(uint32_t*)(sHid + row * 136 + cc) =
                        pack_h2(__float2half_rn(y0), __float2half_rn(y1));
                }
            }

        // ===== Phase B: gemm2 kh0  (W2k0 in buf1) =====
        mbar_wait(mb1, p1); p1 ^= 1;
        __syncthreads();
        fill_w_bulk(sbW0, w1l + WCHUNK, mb0, tid);     // prefetch W1 chunk1
        ACC_CLEAR(acc);
        gemm_tile(sbHid, sbW1, acc, wm, wn, a_r, a_k, b_r, b_k);
#pragma unroll
        for (int mi = 0; mi < 2; mi++)
#pragma unroll
            for (int nj = 0; nj < 4; nj++) {
                int cc = wn + nj * 8 + 2 * t4;
                float bv0 = __ldg(b2 + l * D + cc);
                float bv1 = __ldg(b2 + l * D + cc + 1);
#pragma unroll
                for (int hh = 0; hh < 2; hh++) {
                    int row = wm + mi * 16 + g + hh * 8;
                    float x0 = acc[mi][nj][2 * hh]     + bv0;
                    float x1 = acc[mi][nj][2 * hh + 1] + bv1;
                    float* pp = sPart + row * PSTRIDE + cc;
                    if (hasPartial) {
                        float2 o = *(const float2*)pp;
                        x0 += o.x; x1 += o.y;
                    }
                    float2 vv = {x0, x1};
                    *(float2*)pp = vv;
                }
            }

        // ===== Phase C: gemm1 ch1  (W1c1 in buf0) =====
        mbar_wait(mb0, p0); p0 ^= 1;
        __syncthreads();
        fill_w_bulk(sbW1, w2l + WCHUNK, mb1, tid);     // prefetch W2 khalf1
        ACC_CLEAR(acc);
        gemm_tile(sbXn, sbW0, acc, wm, wn, a_r, a_k, b_r, b_k);
#pragma unroll
        for (int mi = 0; mi < 2; mi++)
#pragma unroll
            for (int nj = 0; nj < 4; nj++) {
                int cc = wn + nj * 8 + 2 * t4;
                float bv0 = __ldg(b1 + l * HDIM + 128 + cc);
                float bv1 = __ldg(b1 + l * HDIM + 128 + cc + 1);
#pragma unroll
                for (int hh = 0; hh < 2; hh++) {
                    int row = wm + mi * 16 + g + hh * 8;
                    float y0 = gelu_f(acc[mi][nj][2 * hh]     + bv0);
                    float y1 = gelu_f(acc[mi][nj][2 * hh + 1] + bv1);
                    *(uint32_t*)(sHid + row * 136 + cc) =
                        pack_h2(__float2half_rn(y0), __float2half_rn(y1));
                }
            }

        // ===== Phase D: gemm2 kh1  (W2k1 in buf1) =====
        mbar_wait(mb1, p1); p1 ^= 1;
        __syncthreads();
        if (l < NLAYER - 2)
            fill_w_bulk(sbW0, g_w1c + (size_t)(l + 1) * 2 * WCHUNK, mb0, tid);  // next W1c0
        ACC_CLEAR(acc);
        gemm_tile(sbHid, sbW1, acc, wm, wn, a_r, a_k, b_r, b_k);
        {
            const int commit = ((l & 3) == 3);
            __half* cb = commit ? (&g_blocks[grp + 1][0] + (size_t)bm * D) : (__half*)0;
#pragma unroll
            for (int mi = 0; mi < 2; mi++)
#pragma unroll
                for (int nj = 0; nj < 4; nj++) {
                    int cc = wn + nj * 8 + 2 * t4;
#pragma unroll
                    for (int hh = 0; hh < 2; hh++) {
                        int row = wm + mi * 16 + g + hh * 8;
                        float* pp = sPart + row * PSTRIDE + cc;
                        float2 o = *(const float2*)pp;
                        float x0 = acc[mi][nj][2 * hh]     + o.x;
                        float x1 = acc[mi][nj][2 * hh + 1] + o.y;
                        float2 vv = {x0, x1};
                        *(float2*)pp = vv;
                        if (commit)
                            *(uint32_t*)(cb + (size_t)row * D + cc) =
                                pack_h2(__float2half_rn(x0), __float2half_rn(x1));
                    }
                }
        }
        __syncthreads();
    }
}

// ======================= prep kernels =======================================
// Coalesced transpose + fp16, writing the PADDED chunk layout (stride 136).
__global__ void transpose_w(const float* __restrict__ W1, const float* __restrict__ W2) {
    __shared__ float tile[32][33];
    int b = blockIdx.x;              // 16 layers * 64 tiles
    int lay = b >> 6, t = b & 63;
    int x = threadIdx.x, y = threadIdx.y;    // (32, 8)
    if (t < 32) {                    // W1: in [128 k][256 n] -> chunks [2][128 n][136 k]
        const float* in = W1 + (size_t)lay * D * HDIM;
        __half* outp = g_w1c + (size_t)lay * 2 * WCHUNK;
        int tr = t >> 3, tc = t & 7;
#pragma unroll
        for (int yy = 0; yy < 4; yy++) {
            int r = y * 4 + yy;
            tile[r][x] = in[(size_t)(tr * 32 + r) * HDIM + tc * 32 + x];
        }
        __syncthreads();
#pragma unroll
        for (int yy = 0; yy < 4; yy++) {
            int r = y * 4 + yy;
            int n = tc * 32 + r, k = tr * 32 + x;
            outp[(size_t)(n >> 7) * WCHUNK + (n & 127) * 136 + k] = __float2half_rn(tile[x][r]);
        }
    } else {                         // W2: in [256 k][128 n] -> chunks [2][128 n][136 k]
        int tt = t - 32;
        const float* in = W2 + (size_t)lay * HDIM * D;
        __half* outp = g_w2c + (size_t)lay * 2 * WCHUNK;
        int tr = tt >> 2, tc = tt & 3;
#pragma unroll
        for (int yy = 0; yy < 4; yy++) {
            int r = y * 4 + yy;
            tile[r][x] = in[(size_t)(tr * 32 + r) * D + tc * 32 + x];
        }
        __syncthreads();
#pragma unroll
        for (int yy = 0; yy < 4; yy++) {
            int r = y * 4 + yy;
            int n = tc * 32 + r, k = tr * 32 + x;
            outp[(size_t)(k >> 7) * WCHUNK + n * 136 + (k & 127)] = __float2half_rn(tile[x][r]);
        }
    }
}

__global__ void conv_emb(const float* __restrict__ emb) {
    const size_t N = (size_t)MTOK * D;
    for (size_t i = (size_t)blockIdx.x * blockDim.x + threadIdx.x; i < N;
         i += (size_t)gridDim.x * blockDim.x)
        g_blocks[0][i] = __float2half_rn(emb[i]);
}

// ======================= host orchestration =================================
extern "C" void kernel_launch(void* const* d_in, const int* in_sizes, int n_in,
                              void* d_out, int out_size) {
    const float* emb  = (const float*)d_in[0];
    const float* w    = (const float*)d_in[1];
    const float* ln_g = (const float*)d_in[2];
    const float* ln_b = (const float*)d_in[3];
    const float* W1   = (const float*)d_in[4];
    const float* b1   = (const float*)d_in[5];
    const float* W2   = (const float*)d_in[6];
    const float* b2   = (const float*)d_in[7];
    float* out = (float*)d_out;

    cudaFuncSetAttribute(fused_net, cudaFuncAttributeMaxDynamicSharedMemorySize, SMEM_TOTAL);

    transpose_w<<<NLAYER * 64, dim3(32, 8)>>>(W1, W2);
    conv_emb<<<512, 256>>>(emb);
    fused_net<<<NCTA, THREADS, SMEM_TOTAL>>>(w, ln_g, ln_b, b1, b2, out);
}

// round 16
// speedup vs baseline: 1.1637x; 1.0431x over previous
#include <cuda_runtime.h>
#include <cuda_fp16.h>
#include <math.h>
#include <stdint.h>

#define MTOK 65536   // 8 * 8192 tokens
#define D    128
#define HDIM 256
#define NLAYER 16
#define TTILE 64             // tokens per CTA
#define NCTA  (MTOK / TTILE) // 1024
#define THREADS 256
#define WCHUNK 17408         // 128*136 halves per weight chunk (34816 B)

// ======================= device global scratch ==============================
__device__ __half g_blocks[5][(size_t)MTOK * D];  // [0]=emb fp16, [1..4]=committed
__device__ __half g_w1c[(size_t)NLAYER * 2 * WCHUNK]; // padded chunks [l][c][128n][136k]
__device__ __half g_w2c[(size_t)NLAYER * 2 * WCHUNK]; // padded chunks [l][c][128n][136k]

// ======================= helpers ============================================
__device__ __forceinline__ uint32_t smem_u32(const void* p) {
    uint32_t a;
    asm("{ .reg .u64 t; cvta.to.shared.u64 t, %1; cvt.u32.u64 %0, t; }" : "=r"(a) : "l"(p));
    return a;
}
__device__ __forceinline__ uint32_t pack_h2(__half a, __half b) {
    return (uint32_t)__half_as_ushort(a) | ((uint32_t)__half_as_ushort(b) << 16);
}
__device__ __forceinline__ void ldm4(uint32_t* r, uint32_t addr) {
    asm volatile("ldmatrix.sync.aligned.m8n8.x4.shared.b16 {%0,%1,%2,%3}, [%4];"
                 : "=r"(r[0]), "=r"(r[1]), "=r"(r[2]), "=r"(r[3]) : "r"(addr));
}
__device__ __forceinline__ void mma16816(float* c, const uint32_t* a,
                                         uint32_t b0, uint32_t b1) {
    asm volatile("mma.sync.aligned.m16n8k16.row.col.f32.f16.f16.f32 "
                 "{%0,%1,%2,%3}, {%4,%5,%6,%7}, {%8,%9}, {%0,%1,%2,%3};"
                 : "+f"(c[0]), "+f"(c[1]), "+f"(c[2]), "+f"(c[3])
                 : "r"(a[0]), "r"(a[1]), "r"(a[2]), "r"(a[3]), "r"(b0), "r"(b1));
}

// ---- bulk-async weight fill (one UBLKCP per 34816-byte chunk) ----
__device__ __forceinline__ void mbar_init(uint32_t mbar, uint32_t cnt) {
    asm volatile("mbarrier.init.shared.b64 [%0], %1;" :: "r"(mbar), "r"(cnt) : "memory");
}
__device__ __forceinline__ void fill_w_bulk(uint32_t dstSmem, const __half* src,
                                            uint32_t mbar, int tid) {
    if (tid == 0) {
        asm volatile("mbarrier.arrive.expect_tx.shared.b64 _, [%0], %1;"
                     :: "r"(mbar), "r"((uint32_t)(WCHUNK * 2)) : "memory");
        asm volatile("cp.async.bulk.shared::cta.global.mbarrier::complete_tx::bytes "
                     "[%0], [%1], %2, [%3];"
                     :: "r"(dstSmem), "l"(src), "r"((uint32_t)(WCHUNK * 2)), "r"(mbar)
                     : "memory");
    }
}
__device__ __forceinline__ void mbar_wait(uint32_t mbar, int phase) {
    uint32_t done;
    do {
        asm volatile("{\n\t.reg .pred p;\n\t"
            "mbarrier.try_wait.parity.shared.b64 p, [%1], %2;\n\t"
            "selp.b32 %0, 1, 0, p;\n\t}" : "=r"(done) : "r"(mbar), "r"((uint32_t)phase)
            : "memory");
    } while (!done);
}

__device__ __forceinline__ float wsum16(float v) {
#pragma unroll
    for (int o = 8; o > 0; o >>= 1) v += __shfl_xor_sync(0xffffffffu, v, o);
    return v;
}

// Fast exact-GELU: branch-free A&S 7.1.26 erf (|abs err| <= 1.5e-7)
__device__ __forceinline__ float gelu_f(float x) {
    float z  = x * 0.70710678118654752f;
    float az = fabsf(z);
    float t  = __frcp_rn(fmaf(0.3275911f, az, 1.0f));
    float p  = fmaf(1.061405429f, t, -1.453152027f);
    p = fmaf(p, t, 1.421413741f);
    p = fmaf(p, t, -0.284496736f);
    p = fmaf(p, t, 0.254829592f);
    p = p * t;
    float e  = __expf(-z * z);
    float er = copysignf(fmaf(-p, e, 1.0f), z);
    return 0.5f * x * (1.0f + er);
}

// ======================= smem layout (per CTA: 104456 B) ====================
#define PSTRIDE 132                     // fp32 partial row stride
#define SP_PART 0                       // fp32 [64][132]           33792
#define SP_XN   33792                   // half [64][136]           17408
#define SP_HID  51200                   // half [64][136]           17408
#define SP_W    68608                   // half [128][136]          34816
#define SP_INV  103424                  // fp32 [4][64]              1024
#define SP_MBAR 104448                  // 1 mbarrier                   8
#define SMEM_TOTAL 104456

// 64x128x128 tile accumulation; A [64 rows] and B [128 n-rows], stride 136.
// 8 warps = 2m x 4n, warp tile 32x32.
__device__ __forceinline__ void gemm_tile(uint32_t sbA, uint32_t sbB,
                                          float acc[2][4][4], int wm, int wn,
                                          int a_r, int a_k, int b_r, int b_k) {
#pragma unroll
    for (int k16 = 0; k16 < 128; k16 += 16) {
        uint32_t a[2][4], b[2][4];
#pragma unroll
        for (int mi = 0; mi < 2; mi++)
            ldm4(a[mi], sbA + (uint32_t)((wm + mi * 16 + a_r) * 136 + k16 + a_k) * 2);
#pragma unroll
        for (int np = 0; np < 2; np++)
            ldm4(b[np], sbB + (uint32_t)((wn + np * 16 + b_r) * 136 + k16 + b_k) * 2);
#pragma unroll
        for (int mi = 0; mi < 2; mi++) {
            mma16816(acc[mi][0], a[mi], b[0][0], b[0][1]);
            mma16816(acc[mi][1], a[mi], b[0][2], b[0][3]);
            mma16816(acc[mi][2], a[mi], b[1][0], b[1][1]);
            mma16816(acc[mi][3], a[mi], b[1][2], b[1][3]);
        }
    }
}

#define ACC_CLEAR(acc)                                 \
    _Pragma("unroll") for (int i = 0; i < 2; i++)      \
    _Pragma("unroll") for (int j = 0; j < 4; j++)      \
    _Pragma("unroll") for (int q = 0; q < 4; q++) acc[i][j][q] = 0.f;

// ======================= fused whole-network kernel =========================
__global__ __launch_bounds__(THREADS, 2)
void fused_net(const float* __restrict__ w, const float* __restrict__ ln_g,
               const float* __restrict__ ln_b, const float* __restrict__ b1,
               const float* __restrict__ b2, float* __restrict__ out) {
    extern __shared__ char smem[];
    float*  sPart = (float*)(smem + SP_PART);
    __half* sXn   = (__half*)(smem + SP_XN);
    __half* sHid  = (__half*)(smem + SP_HID);
    float*  sInv  = (float*)(smem + SP_INV);
    const uint32_t sbXn  = smem_u32(sXn);
    const uint32_t sbHid = smem_u32(sHid);
    const uint32_t sbW   = smem_u32(smem + SP_W);
    const uint32_t mb    = smem_u32(smem + SP_MBAR);

    const int tid  = threadIdx.x;
    const int wid  = tid >> 5;
    const int lane = tid & 31;
    const int bm   = blockIdx.x * TTILE;

    // warp tiling: 8 warps = 2m x 4n, warp tile 32x32 over 64x128
    const int wm = (wid & 1) * 32;
    const int wn = (wid >> 1) * 32;
    const int a_r = (lane & 15);
    const int a_k = (lane >> 4) << 3;
    const int b_r = (lane & 7) + ((lane >> 4) << 3);
    const int b_k = ((lane >> 3) & 1) << 3;
    const int g  = lane >> 2;
    const int t4 = lane & 3;

    // mix coords: 16 lanes/token, 8 dims/lane, 16 tokens per pass (4 passes)
    const int mtok0 = tid >> 4;
    const int l16   = tid & 15;

    const __half* gb = &g_blocks[0][0];
    int p = 0;   // mbarrier phase

    if (tid == 0) mbar_init(mb, 1);
    __syncthreads();
    // prefetch layer-0 W1 chunk0
    fill_w_bulk(sbW, g_w1c, mb, tid);

    for (int l = 0; l < NLAYER; l++) {
        const int grp = l >> 2;
        const int hasPartial = (l & 3) != 0;
        const int nsg = 1 + grp;
        const __half* w1l = g_w1c + (size_t)l * 2 * WCHUNK;
        const __half* w2l = g_w2c + (size_t)l * 2 * WCHUNK;

        // ---------------- mix phase (software-pipelined source loads) -------
        {
            const float* wrow = w + l * D;
            float wv[8], gg[8], bb[8];
            {
                float4 a0 = *(const float4*)(wrow + l16 * 8);
                float4 a1 = *(const float4*)(wrow + l16 * 8 + 4);
                wv[0]=a0.x; wv[1]=a0.y; wv[2]=a0.z; wv[3]=a0.w;
                wv[4]=a1.x; wv[5]=a1.y; wv[6]=a1.z; wv[7]=a1.w;
            }
            if (l < NLAYER - 1) {
                float4 a0 = *(const float4*)(ln_g + l * D + l16 * 8);
                float4 a1 = *(const float4*)(ln_g + l * D + l16 * 8 + 4);
                gg[0]=a0.x; gg[1]=a0.y; gg[2]=a0.z; gg[3]=a0.w;
                gg[4]=a1.x; gg[5]=a1.y; gg[6]=a1.z; gg[7]=a1.w;
                float4 c0 = *(const float4*)(ln_b + l * D + l16 * 8);
                float4 c1 = *(const float4*)(ln_b + l * D + l16 * 8 + 4);
                bb[0]=c0.x; bb[1]=c0.y; bb[2]=c0.z; bb[3]=c0.w;
                bb[4]=c1.x; bb[5]=c1.y; bb[6]=c1.z; bb[7]=c1.w;
            }

            // preload iteration 0's gmem sources
            uint4 raw[4];
#pragma unroll
            for (int i = 0; i < 4; i++)
                if (i < nsg)
                    raw[i] = *(const uint4*)(gb + ((size_t)i * MTOK + bm + mtok0) * D + l16 * 8);

#pragma unroll 1
            for (int it = 0; it < 4; it++) {
                int tg = it * 16 + mtok0;
                uint4 cur[4];
#pragma unroll
                for (int i = 0; i < 4; i++) if (i < nsg) cur[i] = raw[i];
                if (it < 3) {
                    int tgn = tg + 16;
#pragma unroll
                    for (int i = 0; i < 4; i++)
                        if (i < nsg)
                            raw[i] = *(const uint4*)(gb + ((size_t)i * MTOK + bm + tgn) * D + l16 * 8);
                }

                float v[5][8];
                float lgt[5];
                int n = 0;
#pragma unroll
                for (int i = 0; i < 4; i++) {
                    if (i < nsg) {
                        const uint32_t* pr = (const uint32_t*)&cur[i];
#pragma unroll
                        for (int q = 0; q < 4; q++) {
                            float2 f = __half22float2(*(const __half2*)&pr[q]);
                            v[i][2 * q] = f.x; v[i][2 * q + 1] = f.y;
                        }
                        float dt = 0.f;
#pragma unroll
                        for (int j = 0; j < 8; j++) dt += wv[j] * v[i][j];
                        float dtr = wsum16(dt);
                        float ir;
                        if (l == 4 * i) {           // source is new: compute + cache
                            float ss = 0.f;
#pragma unroll
                            for (int j = 0; j < 8; j++) ss += v[i][j] * v[i][j];
                            ss = wsum16(ss);
                            ir = rsqrtf(ss * (1.0f / D) + 1e-8f);
                            if (l16 == 0) sInv[i * TTILE + tg] = ir;
                        } else {
                            ir = sInv[i * TTILE + tg];
                        }
                        lgt[i] = dtr * ir;
                        n++;
                    }
                }
                if (hasPartial) {
                    const float* pp = sPart + tg * PSTRIDE + l16 * 8;
                    float4 p0v = *(const float4*)pp;
                    float4 p1v = *(const float4*)(pp + 4);
                    v[n][0]=p0v.x; v[n][1]=p0v.y; v[n][2]=p0v.z; v[n][3]=p0v.w;
                    v[n][4]=p1v.x; v[n][5]=p1v.y; v[n][6]=p1v.z; v[n][7]=p1v.w;
                    float ss = 0.f, dt = 0.f;
#pragma unroll
                    for (int j = 0; j < 8; j++) { ss += v[n][j]*v[n][j]; dt += wv[j]*v[n][j]; }
                    ss = wsum16(ss);
                    dt = wsum16(dt);
                    lgt[n] = dt * rsqrtf(ss * (1.0f / D) + 1e-8f);
                    n++;
                }
                float mx = -1e30f;
#pragma unroll
                for (int i = 0; i < 5; i++) if (i < n) mx = fmaxf(mx, lgt[i]);
                float se = 0.f;
#pragma unroll
                for (int i = 0; i < 5; i++) if (i < n) { lgt[i] = __expf(lgt[i] - mx); se += lgt[i]; }
                float inv = __frcp_rn(se);
                float h[8];
#pragma unroll
                for (int j = 0; j < 8; j++) h[j] = 0.f;
#pragma unroll
                for (int i = 0; i < 5; i++) if (i < n) {
                    float wt = lgt[i] * inv;
#pragma unroll
                    for (int j = 0; j < 8; j++) h[j] += wt * v[i][j];
                }

                if (l == NLAYER - 1) {
                    float* op = out + (size_t)(bm + tg) * D + l16 * 8;
                    float4 o0 = {h[0], h[1], h[2], h[3]};
                    float4 o1 = {h[4], h[5], h[6], h[7]};
                    *(float4*)op = o0;
                    *(float4*)(op + 4) = o1;
                } else {
                    float s = 0.f;
#pragma unroll
                    for (int j = 0; j < 8; j++) s += h[j];
                    float mu = wsum16(s) * (1.0f / D);
                    float vs = 0.f;
#pragma unroll
                    for (int j = 0; j < 8; j++) { float d0 = h[j] - mu; vs += d0 * d0; }
                    float var = wsum16(vs) * (1.0f / D);
                    float r = rsqrtf(var + 1e-5f);
                    uint32_t pk[4];
#pragma unroll
                    for (int q = 0; q < 4; q++) {
                        float o0 = (h[2*q]   - mu) * r * gg[2*q]   + bb[2*q];
                        float o1 = (h[2*q+1] - mu) * r * gg[2*q+1] + bb[2*q+1];
                        pk[q] = pack_h2(__float2half_rn(o0), __float2half_rn(o1));
                    }
                    *(uint2*)(sXn + tg * 136 + l16 * 8)     = make_uint2(pk[0], pk[1]);
                    *(uint2*)(sXn + tg * 136 + l16 * 8 + 4) = make_uint2(pk[2], pk[3]);
                }
            }
        }
        if (l == NLAYER - 1) return;

        float acc[2][4][4];

        // ===== Phase A: gemm1 ch0 (W1c0) =====
        mbar_wait(mb, p); p ^= 1;
        __syncthreads();                       // sXn + W visible
        ACC_CLEAR(acc);
        gemm_tile(sbXn, sbW, acc, wm, wn, a_r, a_k, b_r, b_k);
        __syncthreads();                       // W consumed
        fill_w_bulk(sbW, w2l, mb, tid);        // W2 khalf0
#pragma unroll
        for (int mi = 0; mi < 2; mi++)
#pragma unroll
            for (int nj = 0; nj < 4; nj++) {
                int cc = wn + nj * 8 + 2 * t4;
                float bv0 = __ldg(b1 + l * HDIM + cc);
                float bv1 = __ldg(b1 + l * HDIM + cc + 1);
#pragma unroll
                for (int hh = 0; hh < 2; hh++) {
                    int row = wm + mi * 16 + g + hh * 8;
                    float y0 = gelu_f(acc[mi][nj][2 * hh]     + bv0);
                    float y1 = gelu_f(acc[mi][nj][2 * hh + 1] + bv1);
                    *(uint32_t*)(sHid + row * 136 + cc) =
                        pack_h2(__float2half_rn(y0), __float2half_rn(y1));
                }
            }

        // ===== Phase B: gemm2 kh0 (W2k0) =====
        mbar_wait(mb, p); p ^= 1;
        __syncthreads();                       // sHid + W visible
        ACC_CLEAR(acc);
        gemm_tile(sbHid, sbW, acc, wm, wn, a_r, a_k, b_r, b_k);
        __syncthreads();
        fill_w_bulk(sbW, w1l + WCHUNK, mb, tid);   // W1 chunk1
#pragma unroll
        for (int mi = 0; mi < 2; mi++)
#pragma unroll
            for (int nj = 0; nj < 4; nj++) {
                int cc = wn + nj * 8 + 2 * t4;
                float bv0 = __ldg(b2 + l * D + cc);
                float bv1 = __ldg(b2 + l * D + cc + 1);
#pragma unroll
                for (int hh = 0; hh < 2; hh++) {
                    int row = wm + mi * 16 + g + hh * 8;
                    float x0 = acc[mi][nj][2 * hh]     + bv0;
                    float x1 = acc[mi][nj][2 * hh + 1] + bv1;
                    float* pp = sPart + row * PSTRIDE + cc;
                    if (hasPartial) {
                        float2 o = *(const float2*)pp;
                        x0 += o.x; x1 += o.y;
                    }
                    float2 vv = {x0, x1};
                    *(float2*)pp = vv;
                }
            }

        // ===== Phase C: gemm1 ch1 (W1c1) =====
        mbar_wait(mb, p); p ^= 1;
        __syncthreads();
        ACC_CLEAR(acc);
        gemm_tile(sbXn, sbW, acc, wm, wn, a_r, a_k, b_r, b_k);
        __syncthreads();
        fill_w_bulk(sbW, w2l + WCHUNK, mb, tid);   // W2 khalf1
#pragma unroll
        for (int mi = 0; mi < 2; mi++)
#pragma unroll
            for (int nj = 0; nj < 4; nj++) {
                int cc = wn + nj * 8 + 2 * t4;
                float bv0 = __ldg(b1 + l * HDIM + 128 + cc);
                float bv1 = __ldg(b1 + l * HDIM + 128 + cc + 1);
#pragma unroll
                for (int hh = 0; hh < 2; hh++) {
                    int row = wm + mi * 16 + g + hh * 8;
                    float y0 = gelu_f(acc[mi][nj][2 * hh]     + bv0);
                    float y1 = gelu_f(acc[mi][nj][2 * hh + 1] + bv1);
                    *(uint32_t*)(sHid + row * 136 + cc) =
                        pack_h2(__float2half_rn(y0), __float2half_rn(y1));
                }
            }

        // ===== Phase D: gemm2 kh1 (W2k1) =====
        mbar_wait(mb, p); p ^= 1;
        __syncthreads();
        ACC_CLEAR(acc);
        gemm_tile(sbHid, sbW, acc, wm, wn, a_r, a_k, b_r, b_k);
        __syncthreads();
        if (l < NLAYER - 2)
            fill_w_bulk(sbW, g_w1c + (size_t)(l + 1) * 2 * WCHUNK, mb, tid);  // next W1c0
        {
            const int commit = ((l & 3) == 3);
            __half* cb = commit ? (&g_blocks[grp + 1][0] + (size_t)bm * D) : (__half*)0;
#pragma unroll
            for (int mi = 0; mi < 2; mi++)
#pragma unroll
                for (int nj = 0; nj < 4; nj++) {
                    int cc = wn + nj * 8 + 2 * t4;
#pragma unroll
                    for (int hh = 0; hh < 2; hh++) {
                        int row = wm + mi * 16 + g + hh * 8;
                        float* pp = sPart + row * PSTRIDE + cc;
                        float2 o = *(const float2*)pp;
                        float x0 = acc[mi][nj][2 * hh]     + o.x;
                        float x1 = acc[mi][nj][2 * hh + 1] + o.y;
                        float2 vv = {x0, x1};
                        *(float2*)pp = vv;
                        if (commit)
                            *(uint32_t*)(cb + (size_t)row * D + cc) =
                                pack_h2(__float2half_rn(x0), __float2half_rn(x1));
                    }
                }
        }
        __syncthreads();                       // partial/commit visible for next mix
    }
}

// ======================= prep kernels =======================================
// Coalesced transpose + fp16, writing the PADDED chunk layout (stride 136).
__global__ void transpose_w(const float* __restrict__ W1, const float* __restrict__ W2) {
    __shared__ float tile[32][33];
    int b = blockIdx.x;              // 16 layers * 64 tiles
    int lay = b >> 6, t = b & 63;
    int x = threadIdx.x, y = threadIdx.y;    // (32, 8)
    if (t < 32) {                    // W1: in [128 k][256 n] -> chunks [2][128 n][136 k]
        const float* in = W1 + (size_t)lay * D * HDIM;
        __half* outp = g_w1c + (size_t)lay * 2 * WCHUNK;
        int tr = t >> 3, tc = t & 7;
#pragma unroll
        for (int yy = 0; yy < 4; yy++) {
            int r = y * 4 + yy;
            tile[r][x] = in[(size_t)(tr * 32 + r) * HDIM + tc * 32 + x];
        }
        __syncthreads();
#pragma unroll
        for (int yy = 0; yy < 4; yy++) {
            int r = y * 4 + yy;
            int n = tc * 32 + r, k = tr * 32 + x;
            outp[(size_t)(n >> 7) * WCHUNK + (n & 127) * 136 + k] = __float2half_rn(tile[x][r]);
        }
    } else {                         // W2: in [256 k][128 n] -> chunks [2][128 n][136 k]
        int tt = t - 32;
        const float* in = W2 + (size_t)lay * HDIM * D;
        __half* outp = g_w2c + (size_t)lay * 2 * WCHUNK;
        int tr = tt >> 2, tc = tt & 3;
#pragma unroll
        for (int yy = 0; yy < 4; yy++) {
            int r = y * 4 + yy;
            tile[r][x] = in[(size_t)(tr * 32 + r) * D + tc * 32 + x];
        }
        __syncthreads();
#pragma unroll
        for (int yy = 0; yy < 4; yy++) {
            int r = y * 4 + yy;
            int n = tc * 32 + r, k = tr * 32 + x;
            outp[(size_t)(k >> 7) * WCHUNK + n * 136 + (k & 127)] = __float2half_rn(tile[x][r]);
        }
    }
}

__global__ void conv_emb(const float* __restrict__ emb) {
    const size_t N = (size_t)MTOK * D;
    for (size_t i = (size_t)blockIdx.x * blockDim.x + threadIdx.x; i < N;
         i += (size_t)gridDim.x * blockDim.x)
        g_blocks[0][i] = __float2half_rn(emb[i]);
}

// ======================= host orchestration =================================
extern "C" void kernel_launch(void* const* d_in, const int* in_sizes, int n_in,
                              void* d_out, int out_size) {
    const float* emb  = (const float*)d_in[0];
    const float* w    = (const float*)d_in[1];
    const float* ln_g = (const float*)d_in[2];
    const float* ln_b = (const float*)d_in[3];
    const float* W1   = (const float*)d_in[4];
    const float* b1   = (const float*)d_in[5];
    const float* W2   = (const float*)d_in[6];
    const float* b2   = (const float*)d_in[7];
    float* out = (float*)d_out;

    cudaFuncSetAttribute(fused_net, cudaFuncAttributeMaxDynamicSharedMemorySize, SMEM_TOTAL);

    transpose_w<<<NLAYER * 64, dim3(32, 8)>>>(W1, W2);
    conv_emb<<<512, 256>>>(emb);
    fused_net<<<NCTA, THREADS, SMEM_TOTAL>>>(w, ln_g, ln_b, b1, b2, out);
}

// round 17
// speedup vs baseline: 1.2738x; 1.0946x over previous
#include <cuda_runtime.h>
#include <cuda_fp16.h>
#include <math.h>
#include <stdint.h>

#define MTOK 65536   // 8 * 8192 tokens
#define D    128
#define HDIM 256
#define NLAYER 16
#define TTILE 64             // tokens per CTA
#define NCTA  (MTOK / TTILE) // 1024
#define THREADS 256
#define WCHUNK 17408         // 128*136 halves per weight chunk (34816 B)

// ======================= device global scratch ==============================
__device__ __half g_blocks[5][(size_t)MTOK * D];  // [0]=emb fp16, [1..4]=committed
__device__ __half g_w1c[(size_t)NLAYER * 2 * WCHUNK]; // padded chunks [l][c][128n][136k]
__device__ __half g_w2c[(size_t)NLAYER * 2 * WCHUNK]; // padded chunks [l][c][128n][136k]

// ======================= helpers ============================================
__device__ __forceinline__ uint32_t smem_u32(const void* p) {
    uint32_t a;
    asm("{ .reg .u64 t; cvta.to.shared.u64 t, %1; cvt.u32.u64 %0, t; }" : "=r"(a) : "l"(p));
    return a;
}
__device__ __forceinline__ uint32_t pack_h2(__half a, __half b) {
    return (uint32_t)__half_as_ushort(a) | ((uint32_t)__half_as_ushort(b) << 16);
}
__device__ __forceinline__ void ldm4(uint32_t* r, uint32_t addr) {
    asm volatile("ldmatrix.sync.aligned.m8n8.x4.shared.b16 {%0,%1,%2,%3}, [%4];"
                 : "=r"(r[0]), "=r"(r[1]), "=r"(r[2]), "=r"(r[3]) : "r"(addr));
}
__device__ __forceinline__ void mma16816(float* c, const uint32_t* a,
                                         uint32_t b0, uint32_t b1) {
    asm volatile("mma.sync.aligned.m16n8k16.row.col.f32.f16.f16.f32 "
                 "{%0,%1,%2,%3}, {%4,%5,%6,%7}, {%8,%9}, {%0,%1,%2,%3};"
                 : "+f"(c[0]), "+f"(c[1]), "+f"(c[2]), "+f"(c[3])
                 : "r"(a[0]), "r"(a[1]), "r"(a[2]), "r"(a[3]), "r"(b0), "r"(b1));
}

// ---- bulk-async weight fill (one UBLKCP per 34816-byte chunk) ----
__device__ __forceinline__ void mbar_init(uint32_t mbar, uint32_t cnt) {
    asm volatile("mbarrier.init.shared.b64 [%0], %1;" :: "r"(mbar), "r"(cnt) : "memory");
}
__device__ __forceinline__ void fill_w_bulk(uint32_t dstSmem, const __half* src,
                                            uint32_t mbar, int tid) {
    if (tid == 0) {
        asm volatile("mbarrier.arrive.expect_tx.shared.b64 _, [%0], %1;"
                     :: "r"(mbar), "r"((uint32_t)(WCHUNK * 2)) : "memory");
        asm volatile("cp.async.bulk.shared::cta.global.mbarrier::complete_tx::bytes "
                     "[%0], [%1], %2, [%3];"
                     :: "r"(dstSmem), "l"(src), "r"((uint32_t)(WCHUNK * 2)), "r"(mbar)
                     : "memory");
    }
}
__device__ __forceinline__ void mbar_wait(uint32_t mbar, int phase) {
    uint32_t done;
    do {
        asm volatile("{\n\t.reg .pred p;\n\t"
            "mbarrier.try_wait.parity.shared.b64 p, [%1], %2;\n\t"
            "selp.b32 %0, 1, 0, p;\n\t}" : "=r"(done) : "r"(mbar), "r"((uint32_t)phase)
            : "memory");
    } while (!done);
}

__device__ __forceinline__ float wsum16(float v) {
#pragma unroll
    for (int o = 8; o > 0; o >>= 1) v += __shfl_xor_sync(0xffffffffu, v, o);
    return v;
}

// Fast exact-GELU: branch-free A&S 7.1.26 erf (|abs err| <= 1.5e-7)
__device__ __forceinline__ float gelu_f(float x) {
    float z  = x * 0.70710678118654752f;
    float az = fabsf(z);
    float t  = __frcp_rn(fmaf(0.3275911f, az, 1.0f));
    float p  = fmaf(1.061405429f, t, -1.453152027f);
    p = fmaf(p, t, 1.421413741f);
    p = fmaf(p, t, -0.284496736f);
    p = fmaf(p, t, 0.254829592f);
    p = p * t;
    float e  = __expf(-z * z);
    float er = copysignf(fmaf(-p, e, 1.0f), z);
    return 0.5f * x * (1.0f + er);
}

// ======================= smem layout (per CTA: 105992 B) ====================
#define PSTRIDE 132                     // fp32 partial row stride
#define SP_PART 0                       // fp32 [64][132]           33792
#define SP_XN   33792                   // half [64][136]           17408
#define SP_HID  51200                   // half [64][136]           17408
#define SP_W    68608                   // half [128][136]          34816
#define SP_INV  103424                  // fp32 [4][64]              1024
#define SP_B1   104448                  // fp32 [256]                1024
#define SP_B2   105472                  // fp32 [128]                 512
#define SP_MBAR 105984                  // 1 mbarrier                   8
#define SMEM_TOTAL 105992

// 64x128x128 tile accumulation; A [64 rows] and B [128 n-rows], stride 136.
// 8 warps = 2m x 4n, warp tile 32x32.
__device__ __forceinline__ void gemm_tile(uint32_t sbA, uint32_t sbB,
                                          float acc[2][4][4], int wm, int wn,
                                          int a_r, int a_k, int b_r, int b_k) {
#pragma unroll
    for (int k16 = 0; k16 < 128; k16 += 16) {
        uint32_t a[2][4], b[2][4];
#pragma unroll
        for (int mi = 0; mi < 2; mi++)
            ldm4(a[mi], sbA + (uint32_t)((wm + mi * 16 + a_r) * 136 + k16 + a_k) * 2);
#pragma unroll
        for (int np = 0; np < 2; np++)
            ldm4(b[np], sbB + (uint32_t)((wn + np * 16 + b_r) * 136 + k16 + b_k) * 2);
#pragma unroll
        for (int mi = 0; mi < 2; mi++) {
            mma16816(acc[mi][0], a[mi], b[0][0], b[0][1]);
            mma16816(acc[mi][1], a[mi], b[0][2], b[0][3]);
            mma16816(acc[mi][2], a[mi], b[1][0], b[1][1]);
            mma16816(acc[mi][3], a[mi], b[1][2], b[1][3]);
        }
    }
}

#define ACC_CLEAR(acc)                                 \
    _Pragma("unroll") for (int i = 0; i < 2; i++)      \
    _Pragma("unroll") for (int j = 0; j < 4; j++)      \
    _Pragma("unroll") for (int q = 0; q < 4; q++) acc[i][j][q] = 0.f;

// ======================= fused whole-network kernel =========================
__global__ __launch_bounds__(THREADS, 2)
void fused_net(const float* __restrict__ w, const float* __restrict__ ln_g,
               const float* __restrict__ ln_b, const float* __restrict__ b1,
               const float* __restrict__ b2, float* __restrict__ out) {
    extern __shared__ char smem[];
    float*  sPart = (float*)(smem + SP_PART);
    __half* sXn   = (__half*)(smem + SP_XN);
    __half* sHid  = (__half*)(smem + SP_HID);
    float*  sInv  = (float*)(smem + SP_INV);
    float*  sB1   = (float*)(smem + SP_B1);
    float*  sB2   = (float*)(smem + SP_B2);
    const uint32_t sbXn  = smem_u32(sXn);
    const uint32_t sbHid = smem_u32(sHid);
    const uint32_t sbW   = smem_u32(smem + SP_W);
    const uint32_t mb    = smem_u32(smem + SP_MBAR);

    const int tid  = threadIdx.x;
    const int wid  = tid >> 5;
    const int lane = tid & 31;
    const int bm   = blockIdx.x * TTILE;

    // warp tiling: 8 warps = 2m x 4n, warp tile 32x32 over 64x128
    const int wm = (wid & 1) * 32;
    const int wn = (wid >> 1) * 32;
    const int a_r = (lane & 15);
    const int a_k = (lane >> 4) << 3;
    const int b_r = (lane & 7) + ((lane >> 4) << 3);
    const int b_k = ((lane >> 3) & 1) << 3;
    const int g  = lane >> 2;
    const int t4 = lane & 3;

    // mix coords: 16 lanes/token, 8 dims/lane, 16 tokens per pass (4 passes)
    const int mtok0 = tid >> 4;
    const int l16   = tid & 15;

    const __half* gb = &g_blocks[0][0];
    int p = 0;   // mbarrier phase

    if (tid == 0) mbar_init(mb, 1);
    __syncthreads();
    // prefetch layer-0 W1 chunk0
    fill_w_bulk(sbW, g_w1c, mb, tid);

    for (int l = 0; l < NLAYER; l++) {
        const int grp = l >> 2;
        const int hasPartial = (l & 3) != 0;
        const int nsg = 1 + grp;
        const __half* w1l = g_w1c + (size_t)l * 2 * WCHUNK;
        const __half* w2l = g_w2c + (size_t)l * 2 * WCHUNK;

        // ---------------- mix phase (software-pipelined source loads) -------
        {
            // stage this layer's biases into smem (covered by mix latency)
            if (l < NLAYER - 1) {
                sB1[tid] = b1[l * HDIM + tid];
                if (tid < D) sB2[tid] = b2[l * D + tid];
            }
            const float* wrow = w + l * D;
            float wv[8], gg[8], bb[8];
            {
                float4 a0 = *(const float4*)(wrow + l16 * 8);
                float4 a1 = *(const float4*)(wrow + l16 * 8 + 4);
                wv[0]=a0.x; wv[1]=a0.y; wv[2]=a0.z; wv[3]=a0.w;
                wv[4]=a1.x; wv[5]=a1.y; wv[6]=a1.z; wv[7]=a1.w;
            }
            if (l < NLAYER - 1) {
                float4 a0 = *(const float4*)(ln_g + l * D + l16 * 8);
                float4 a1 = *(const float4*)(ln_g + l * D + l16 * 8 + 4);
                gg[0]=a0.x; gg[1]=a0.y; gg[2]=a0.z; gg[3]=a0.w;
                gg[4]=a1.x; gg[5]=a1.y; gg[6]=a1.z; gg[7]=a1.w;
                float4 c0 = *(const float4*)(ln_b + l * D + l16 * 8);
                float4 c1 = *(const float4*)(ln_b + l * D + l16 * 8 + 4);
                bb[0]=c0.x; bb[1]=c0.y; bb[2]=c0.z; bb[3]=c0.w;
                bb[4]=c1.x; bb[5]=c1.y; bb[6]=c1.z; bb[7]=c1.w;
            }

            // preload iteration 0's gmem sources
            uint4 raw[4];
#pragma unroll
            for (int i = 0; i < 4; i++)
                if (i < nsg)
                    raw[i] = *(const uint4*)(gb + ((size_t)i * MTOK + bm + mtok0) * D + l16 * 8);

#pragma unroll 1
            for (int it = 0; it < 4; it++) {
                int tg = it * 16 + mtok0;
                uint4 cur[4];
#pragma unroll
                for (int i = 0; i < 4; i++) if (i < nsg) cur[i] = raw[i];
                if (it < 3) {
                    int tgn = tg + 16;
#pragma unroll
                    for (int i = 0; i < 4; i++)
                        if (i < nsg)
                            raw[i] = *(const uint4*)(gb + ((size_t)i * MTOK + bm + tgn) * D + l16 * 8);
                }

                float v[5][8];
                float lgt[5];
                int n = 0;
#pragma unroll
                for (int i = 0; i < 4; i++) {
                    if (i < nsg) {
                        const uint32_t* pr = (const uint32_t*)&cur[i];
#pragma unroll
                        for (int q = 0; q < 4; q++) {
                            float2 f = __half22float2(*(const __half2*)&pr[q]);
                            v[i][2 * q] = f.x; v[i][2 * q + 1] = f.y;
                        }
                        float dt = 0.f;
#pragma unroll
                        for (int j = 0; j < 8; j++) dt += wv[j] * v[i][j];
                        float dtr = wsum16(dt);
                        float ir;
                        if (l == 4 * i) {           // source is new: compute + cache
                            float ss = 0.f;
#pragma unroll
                            for (int j = 0; j < 8; j++) ss += v[i][j] * v[i][j];
                            ss = wsum16(ss);
                            ir = rsqrtf(ss * (1.0f / D) + 1e-8f);
                            if (l16 == 0) sInv[i * TTILE + tg] = ir;
                        } else {
                            ir = sInv[i * TTILE + tg];
                        }
                        lgt[i] = dtr * ir;
                        n++;
                    }
                }
                if (hasPartial) {
                    const float* pp = sPart + tg * PSTRIDE + l16 * 8;
                    float4 p0v = *(const float4*)pp;
                    float4 p1v = *(const float4*)(pp + 4);
                    v[n][0]=p0v.x; v[n][1]=p0v.y; v[n][2]=p0v.z; v[n][3]=p0v.w;
                    v[n][4]=p1v.x; v[n][5]=p1v.y; v[n][6]=p1v.z; v[n][7]=p1v.w;
                    float ss = 0.f, dt = 0.f;
#pragma unroll
                    for (int j = 0; j < 8; j++) { ss += v[n][j]*v[n][j]; dt += wv[j]*v[n][j]; }
                    ss = wsum16(ss);
                    dt = wsum16(dt);
                    lgt[n] = dt * rsqrtf(ss * (1.0f / D) + 1e-8f);
                    n++;
                }
                // softmax without max-shift: |logits| << 1, numerically safe
                float se = 0.f;
#pragma unroll
                for (int i = 0; i < 5; i++) if (i < n) { lgt[i] = __expf(lgt[i]); se += lgt[i]; }
                float inv = __frcp_rn(se);
                float h[8];
#pragma unroll
                for (int j = 0; j < 8; j++) h[j] = 0.f;
#pragma unroll
                for (int i = 0; i < 5; i++) if (i < n) {
                    float wt = lgt[i] * inv;
#pragma unroll
                    for (int j = 0; j < 8; j++) h[j] += wt * v[i][j];
                }

                if (l == NLAYER - 1) {
                    float* op = out + (size_t)(bm + tg) * D + l16 * 8;
                    float4 o0 = {h[0], h[1], h[2], h[3]};
                    float4 o1 = {h[4], h[5], h[6], h[7]};
                    *(float4*)op = o0;
                    *(float4*)(op + 4) = o1;
                } else {
                    float s = 0.f;
#pragma unroll
                    for (int j = 0; j < 8; j++) s += h[j];
                    float mu = wsum16(s) * (1.0f / D);
                    float vs = 0.f;
#pragma unroll
                    for (int j = 0; j < 8; j++) { float d0 = h[j] - mu; vs += d0 * d0; }
                    float var = wsum16(vs) * (1.0f / D);
                    float r = rsqrtf(var + 1e-5f);
                    uint32_t pk[4];
#pragma unroll
                    for (int q = 0; q < 4; q++) {
                        float o0 = (h[2*q]   - mu) * r * gg[2*q]   + bb[2*q];
                        float o1 = (h[2*q+1] - mu) * r * gg[2*q+1] + bb[2*q+1];
                        pk[q] = pack_h2(__float2half_rn(o0), __float2half_rn(o1));
                    }
                    *(uint2*)(sXn + tg * 136 + l16 * 8)     = make_uint2(pk[0], pk[1]);
                    *(uint2*)(sXn + tg * 136 + l16 * 8 + 4) = make_uint2(pk[2], pk[3]);
                }
            }
        }
        if (l == NLAYER - 1) return;

        float acc[2][4][4];

        // ===== Phase A: gemm1 ch0 (W1c0) =====
        mbar_wait(mb, p); p ^= 1;
        __syncthreads();                       // sXn + W + biases visible
        ACC_CLEAR(acc);
        gemm_tile(sbXn, sbW, acc, wm, wn, a_r, a_k, b_r, b_k);
        __syncthreads();                       // W consumed
        fill_w_bulk(sbW, w2l, mb, tid);        // W2 khalf0
#pragma unroll
        for (int mi = 0; mi < 2; mi++)
#pragma unroll
            for (int nj = 0; nj < 4; nj++) {
                int cc = wn + nj * 8 + 2 * t4;
                float bv0 = sB1[cc], bv1 = sB1[cc + 1];
#pragma unroll
                for (int hh = 0; hh < 2; hh++) {
                    int row = wm + mi * 16 + g + hh * 8;
                    float y0 = gelu_f(acc[mi][nj][2 * hh]     + bv0);
                    float y1 = gelu_f(acc[mi][nj][2 * hh + 1] + bv1);
                    *(uint32_t*)(sHid + row * 136 + cc) =
                        pack_h2(__float2half_rn(y0), __float2half_rn(y1));
                }
            }

        // ===== Phase B: gemm2 kh0 (W2k0) =====
        mbar_wait(mb, p); p ^= 1;
        __syncthreads();                       // sHid + W visible
        ACC_CLEAR(acc);
        gemm_tile(sbHid, sbW, acc, wm, wn, a_r, a_k, b_r, b_k);
        __syncthreads();
        fill_w_bulk(sbW, w1l + WCHUNK, mb, tid);   // W1 chunk1
#pragma unroll
        for (int mi = 0; mi < 2; mi++)
#pragma unroll
            for (int nj = 0; nj < 4; nj++) {
                int cc = wn + nj * 8 + 2 * t4;
                float bv0 = sB2[cc], bv1 = sB2[cc + 1];
#pragma unroll
                for (int hh = 0; hh < 2; hh++) {
                    int row = wm + mi * 16 + g + hh * 8;
                    float x0 = acc[mi][nj][2 * hh]     + bv0;
                    float x1 = acc[mi][nj][2 * hh + 1] + bv1;
                    float* pp = sPart + row * PSTRIDE + cc;
                    if (hasPartial) {
                        float2 o = *(const float2*)pp;
                        x0 += o.x; x1 += o.y;
                    }
                    float2 vv = {x0, x1};
                    *(float2*)pp = vv;
                }
            }

        // ===== Phase C: gemm1 ch1 (W1c1) =====
        mbar_wait(mb, p); p ^= 1;
        __syncthreads();
        ACC_CLEAR(acc);
        gemm_tile(sbXn, sbW, acc, wm, wn, a_r, a_k, b_r, b_k);
        __syncthreads();
        fill_w_bulk(sbW, w2l + WCHUNK, mb, tid);   // W2 khalf1
#pragma unroll
        for (int mi = 0; mi < 2; mi++)
#pragma unroll
            for (int nj = 0; nj < 4; nj++) {
                int cc = wn + nj * 8 + 2 * t4;
                float bv0 = sB1[128 + cc], bv1 = sB1[128 + cc + 1];
#pragma unroll
                for (int hh = 0; hh < 2; hh++) {
                    int row = wm + mi * 16 + g + hh * 8;
                    float y0 = gelu_f(acc[mi][nj][2 * hh]     + bv0);
                    float y1 = gelu_f(acc[mi][nj][2 * hh + 1] + bv1);
                    *(uint32_t*)(sHid + row * 136 + cc) =
                        pack_h2(__float2half_rn(y0), __float2half_rn(y1));
                }
            }

        // ===== Phase D: gemm2 kh1 (W2k1) =====
        mbar_wait(mb, p); p ^= 1;
        __syncthreads();
        ACC_CLEAR(acc);
        gemm_tile(sbHid, sbW, acc, wm, wn, a_r, a_k, b_r, b_k);
        __syncthreads();
        if (l < NLAYER - 2)
            fill_w_bulk(sbW, g_w1c + (size_t)(l + 1) * 2 * WCHUNK, mb, tid);  // next W1c0
        {
            const int commit = ((l & 3) == 3);
            __half* cb = commit ? (&g_blocks[grp + 1][0] + (size_t)bm * D) : (__half*)0;
#pragma unroll
            for (int mi = 0; mi < 2; mi++)
#pragma unroll
                for (int nj = 0; nj < 4; nj++) {
                    int cc = wn + nj * 8 + 2 * t4;
#pragma unroll
                    for (int hh = 0; hh < 2; hh++) {
                        int row = wm + mi * 16 + g + hh * 8;
                        float* pp = sPart + row * PSTRIDE + cc;
                        float2 o = *(const float2*)pp;
                        float x0 = acc[mi][nj][2 * hh]     + o.x;
                        float x1 = acc[mi][nj][2 * hh + 1] + o.y;
                        float2 vv = {x0, x1};
                        *(float2*)pp = vv;
                        if (commit)
                            *(uint32_t*)(cb + (size_t)row * D + cc) =
                                pack_h2(__float2half_rn(x0), __float2half_rn(x1));
                    }
                }
        }
        __syncthreads();                       // partial/commit visible for next mix
    }
}

// ======================= prep kernels =======================================
// Coalesced transpose + fp16, writing the PADDED chunk layout (stride 136).
__global__ void transpose_w(const float* __restrict__ W1, const float* __restrict__ W2) {
    __shared__ float tile[32][33];
    int b = blockIdx.x;              // 16 layers * 64 tiles
    int lay = b >> 6, t = b & 63;
    int x = threadIdx.x, y = threadIdx.y;    // (32, 8)
    if (t < 32) {                    // W1: in [128 k][256 n] -> chunks [2][128 n][136 k]
        const float* in = W1 + (size_t)lay * D * HDIM;
        __half* outp = g_w1c + (size_t)lay * 2 * WCHUNK;
        int tr = t >> 3, tc = t & 7;
#pragma unroll
        for (int yy = 0; yy < 4; yy++) {
            int r = y * 4 + yy;
            tile[r][x] = in[(size_t)(tr * 32 + r) * HDIM + tc * 32 + x];
        }
        __syncthreads();
#pragma unroll
        for (int yy = 0; yy < 4; yy++) {
            int r = y * 4 + yy;
            int n = tc * 32 + r, k = tr * 32 + x;
            outp[(size_t)(n >> 7) * WCHUNK + (n & 127) * 136 + k] = __float2half_rn(tile[x][r]);
        }
    } else {                         // W2: in [256 k][128 n] -> chunks [2][128 n][136 k]
        int tt = t - 32;
        const float* in = W2 + (size_t)lay * HDIM * D;
        __half* outp = g_w2c + (size_t)lay * 2 * WCHUNK;
        int tr = tt >> 2, tc = tt & 3;
#pragma unroll
        for (int yy = 0; yy < 4; yy++) {
            int r = y * 4 + yy;
            tile[r][x] = in[(size_t)(tr * 32 + r) * D + tc * 32 + x];
        }
        __syncthreads();
#pragma unroll
        for (int yy = 0; yy < 4; yy++) {
            int r = y * 4 + yy;
            int n = tc * 32 + r, k = tr * 32 + x;
            outp[(size_t)(k >> 7) * WCHUNK + n * 136 + (k & 127)] = __float2half_rn(tile[x][r]);
        }
    }
}

__global__ void conv_emb(const float* __restrict__ emb) {
    const size_t N = (size_t)MTOK * D;
    for (size_t i = (size_t)blockIdx.x * blockDim.x + threadIdx.x; i < N;
         i += (size_t)gridDim.x * blockDim.x)
        g_blocks[0][i] = __float2half_rn(emb[i]);
}

// ======================= host orchestration =================================
extern "C" void kernel_launch(void* const* d_in, const int* in_sizes, int n_in,
                              void* d_out, int out_size) {
    const float* emb  = (const float*)d_in[0];
    const float* w    = (const float*)d_in[1];
    const float* ln_g = (const float*)d_in[2];
    const float* ln_b = (const float*)d_in[3];
    const float* W1   = (const float*)d_in[4];
    const float* b1   = (const float*)d_in[5];
    const float* W2   = (const float*)d_in[6];
    const float* b2   = (const float*)d_in[7];
    float* out = (float*)d_out;

    cudaFuncSetAttribute(fused_net, cudaFuncAttributeMaxDynamicSharedMemorySize, SMEM_TOTAL);

    transpose_w<<<NLAYER * 64, dim3(32, 8)>>>(W1, W2);
    conv_emb<<<512, 256>>>(emb);
    fused_net<<<NCTA, THREADS, SMEM_TOTAL>>>(w, ln_g, ln_b, b1, b2, out);
}